// round 1
// baseline (speedup 1.0000x reference)
#include <cuda_runtime.h>

#define N_NODES 20000
#define N_EDGES 200000
#define N_TRIP  400000
#define HID 128
#define DOWN 32
#define CO 64
#define DR 16

// ---------------- device scratch (no allocations allowed) ----------------
__device__ float g_xd[N_NODES * DOWN];          // 2.56 MB
__device__ float g_c[N_NODES * DR * DOWN];      // 40.96 MB
__device__ float g_tw[N_EDGES * DR * DOWN];     // 409.6 MB
__device__ float g_agg[N_NODES * DOWN];         // 2.56 MB

__device__ __forceinline__ float silu_f(float v) {
    return v / (1.0f + __expf(-v));
}

__device__ __forceinline__ float warp_sum32(float s) {
    s += __shfl_xor_sync(0xffffffffu, s, 16);
    s += __shfl_xor_sync(0xffffffffu, s, 8);
    s += __shfl_xor_sync(0xffffffffu, s, 4);
    s += __shfl_xor_sync(0xffffffffu, s, 2);
    s += __shfl_xor_sync(0xffffffffu, s, 1);
    return s;
}

// ---------------- zero tw + agg (must re-zero every graph replay) --------
// 25,600,000 float4 for tw + 160,000 float4 for agg = 25,760,000 = 256*100625
__global__ void zero_all_kernel() {
    int i = blockIdx.x * blockDim.x + threadIdx.x;
    float4 z = make_float4(0.f, 0.f, 0.f, 0.f);
    if (i < 25600000) {
        reinterpret_cast<float4*>(g_tw)[i] = z;
    } else {
        reinterpret_cast<float4*>(g_agg)[i - 25600000] = z;
    }
}

// ---------------- K1: node MLP  x -> x_d [N,32] --------------------------
// block = 128 threads, 16 nodes per block, W1/W2 in shared
__global__ void node_mlp_kernel(const float* __restrict__ x,
                                const float* __restrict__ W1,
                                const float* __restrict__ b1,
                                const float* __restrict__ W2,
                                const float* __restrict__ b2) {
    extern __shared__ float sm[];
    float* sW1 = sm;              // 16384
    float* sW2 = sm + 16384;      // 4096
    float* sb1 = sm + 20480;      // 128
    float* sb2 = sm + 20608;      // 32
    float* h0  = sm + 20640;      // 512  (transposed [k][4 rows])
    float* h1  = sm + 21152;      // 512

    int t = threadIdx.x;
    for (int i = t; i < 16384; i += 128) sW1[i] = W1[i];
    for (int i = t; i < 4096;  i += 128) sW2[i] = W2[i];
    if (t < 128) sb1[t] = b1[t];
    if (t < 32)  sb2[t] = b2[t];
    __syncthreads();

    int base = blockIdx.x * 16;
    for (int n0 = 0; n0 < 16; n0 += 4) {
        float4 hv;
        hv.x = silu_f(x[(base + n0 + 0) * HID + t]);
        hv.y = silu_f(x[(base + n0 + 1) * HID + t]);
        hv.z = silu_f(x[(base + n0 + 2) * HID + t]);
        hv.w = silu_f(x[(base + n0 + 3) * HID + t]);
        *reinterpret_cast<float4*>(&h0[t * 4]) = hv;
        __syncthreads();

        float4 acc = make_float4(sb1[t], sb1[t], sb1[t], sb1[t]);
        #pragma unroll 8
        for (int k = 0; k < 128; k++) {
            float w = sW1[k * 128 + t];
            float4 h = *reinterpret_cast<const float4*>(&h0[k * 4]);
            acc.x = fmaf(h.x, w, acc.x);
            acc.y = fmaf(h.y, w, acc.y);
            acc.z = fmaf(h.z, w, acc.z);
            acc.w = fmaf(h.w, w, acc.w);
        }
        float4 s1 = make_float4(silu_f(acc.x), silu_f(acc.y), silu_f(acc.z), silu_f(acc.w));
        *reinterpret_cast<float4*>(&h1[t * 4]) = s1;
        __syncthreads();

        if (t < 32) {
            float4 a2 = make_float4(sb2[t], sb2[t], sb2[t], sb2[t]);
            #pragma unroll 8
            for (int k = 0; k < 128; k++) {
                float w = sW2[k * 32 + t];
                float4 h = *reinterpret_cast<const float4*>(&h1[k * 4]);
                a2.x = fmaf(h.x, w, a2.x);
                a2.y = fmaf(h.y, w, a2.y);
                a2.z = fmaf(h.z, w, a2.z);
                a2.w = fmaf(h.w, w, a2.w);
            }
            g_xd[(base + n0 + 0) * DOWN + t] = a2.x;
            g_xd[(base + n0 + 1) * DOWN + t] = a2.y;
            g_xd[(base + n0 + 2) * DOWN + t] = a2.z;
            g_xd[(base + n0 + 3) * DOWN + t] = a2.w;
        }
        __syncthreads();
    }
}

// ---------------- K2: coeffs MLP  coeffs -> c [N*16,32] ------------------
// rows = N*DR = 320000; block = 128 threads, 16 rows per block
#define H0S 20
#define H1S 20
__global__ void co_mlp_kernel(const float* __restrict__ cin,
                              const float* __restrict__ W1,
                              const float* __restrict__ W2) {
    extern __shared__ float sm[];
    float* sW1 = sm;              // 64*128 = 8192
    float* sW2 = sm + 8192;       // 128*32 = 4096
    float* h0  = sm + 12288;      // 64*20 = 1280 (padded stride)
    float* h1  = sm + 13568;      // 128*20 = 2560

    int t = threadIdx.x;
    for (int i = t; i < 8192; i += 128) sW1[i] = W1[i];
    for (int i = t; i < 4096; i += 128) sW2[i] = W2[i];

    int baserow = blockIdx.x * 16;
    for (int i = t; i < 1024; i += 128) {
        int rr = i >> 6, k = i & 63;
        h0[k * H0S + rr] = silu_f(cin[(baserow + rr) * CO + k]);
    }
    __syncthreads();

    // layer 1: 64 -> 128 (silu), process rows in chunks of 4
    for (int c = 0; c < 4; c++) {
        float4 acc = make_float4(0.f, 0.f, 0.f, 0.f);
        #pragma unroll 8
        for (int k = 0; k < 64; k++) {
            float w = sW1[k * 128 + t];
            float4 h = *reinterpret_cast<const float4*>(&h0[k * H0S + c * 4]);
            acc.x = fmaf(h.x, w, acc.x);
            acc.y = fmaf(h.y, w, acc.y);
            acc.z = fmaf(h.z, w, acc.z);
            acc.w = fmaf(h.w, w, acc.w);
        }
        float4 s = make_float4(silu_f(acc.x), silu_f(acc.y), silu_f(acc.z), silu_f(acc.w));
        *reinterpret_cast<float4*>(&h1[t * H1S + c * 4]) = s;
    }
    __syncthreads();

    // layer 2: 128 -> 32; warp g handles rows g*4..g*4+3, lane = out col
    int g = t >> 5, j = t & 31;
    float4 acc = make_float4(0.f, 0.f, 0.f, 0.f);
    #pragma unroll 8
    for (int k = 0; k < 128; k++) {
        float w = sW2[k * 32 + j];
        float4 h = *reinterpret_cast<const float4*>(&h1[k * H1S + g * 4]);
        acc.x = fmaf(h.x, w, acc.x);
        acc.y = fmaf(h.y, w, acc.y);
        acc.z = fmaf(h.z, w, acc.z);
        acc.w = fmaf(h.w, w, acc.w);
    }
    g_c[(baserow + g * 4 + 0) * DOWN + j] = acc.x;
    g_c[(baserow + g * 4 + 1) * DOWN + j] = acc.y;
    g_c[(baserow + g * 4 + 2) * DOWN + j] = acc.z;
    g_c[(baserow + g * 4 + 3) * DOWN + j] = acc.w;
}

// ---------------- K3: triplet -> tw atomics -------------------------------
// warp per triplet, lane = DOWN index
__global__ void triplet_kernel(const float* __restrict__ robs,
                               const float* __restrict__ shbs,
                               const int* __restrict__ idx_j,
                               const int* __restrict__ idx_k,
                               const int* __restrict__ e_kj,
                               const int* __restrict__ e_ji) {
    int wid  = (blockIdx.x * blockDim.x + threadIdx.x) >> 5;
    int lane = threadIdx.x & 31;
    if (wid >= N_TRIP) return;

    int j  = idx_j[wid];
    int k  = idx_k[wid];
    int kj = e_kj[wid];
    int ji = e_ji[wid];

    const float* ck = g_c + (size_t)k * (DR * DOWN);
    const float* cj = g_c + (size_t)j * (DR * DOWN);

    float v[DR];
    #pragma unroll
    for (int r = 0; r < DR; r++) {
        float a = ck[r * DOWN + lane];
        float b = cj[r * DOWN + lane];
        v[r] = fmaf(a, b, a);              // c_k*c_j + c_k
    }

    float wl = 0.f;
    if (lane < DR) wl = shbs[wid * DR + lane] * robs[kj * DR + lane];

    float* twp = g_tw + (size_t)ji * (DR * DOWN);
    #pragma unroll
    for (int r = 0; r < DR; r++) {
        float s = warp_sum32(v[r] * v[r]);
        float wr = __shfl_sync(0xffffffffu, wl, r);
        float scale = wr / fmaxf(sqrtf(s), 1e-12f);
        atomicAdd(&twp[r * DOWN + lane], v[r] * scale);
    }
}

// ---------------- K4: edge interaction + node aggregation ----------------
// warp per edge, lane = DOWN index
__global__ void edge_kernel(const float* __restrict__ robs,
                            const int* __restrict__ edge_index) {
    int wid  = (blockIdx.x * blockDim.x + threadIdx.x) >> 5;
    int lane = threadIdx.x & 31;
    if (wid >= N_EDGES) return;

    int src = edge_index[wid];              // edge_index[0]
    int dst = edge_index[N_EDGES + wid];    // edge_index[1]

    const float* cd  = g_c + (size_t)dst * (DR * DOWN);
    const float* cs  = g_c + (size_t)src * (DR * DOWN);
    const float* twp = g_tw + (size_t)wid * (DR * DOWN);

    float rl = (lane < DR) ? robs[wid * DR + lane] : 0.f;

    float acc = 0.f;
    #pragma unroll
    for (int r = 0; r < DR; r++) {
        float a = cd[r * DOWN + lane];
        float b = cs[r * DOWN + lane];
        float v = fmaf(a, b, a) * twp[r * DOWN + lane];   // (cd*cs+cd)*tw
        float s = warp_sum32(v * v);
        float inv = 1.f / fmaxf(sqrtf(s), 1e-12f);
        float wr = __shfl_sync(0xffffffffu, rl, r);
        acc = fmaf(wr, v * inv, acc);                     // robs . coeffs_ji
    }

    float s2 = warp_sum32(acc * acc);
    float rd = acc / fmaxf(sqrtf(s2), 1e-12f);            // normalized r

    atomicAdd(&g_agg[src * DOWN + lane], g_xd[dst * DOWN + lane] * rd);
}

// ---------------- K5: up-projection  agg @ W_up -> out [N,128] ------------
__global__ void up_kernel(const float* __restrict__ Wup,
                          float* __restrict__ out) {
    __shared__ float sW[DOWN * HID];   // 4096
    __shared__ float sA[16 * DOWN];    // 512
    int t = threadIdx.x;
    for (int i = t; i < DOWN * HID; i += 128) sW[i] = Wup[i];
    int base = blockIdx.x * 16;
    for (int i = t; i < 512; i += 128) sA[i] = g_agg[base * DOWN + i];
    __syncthreads();

    for (int n = 0; n < 16; n++) {
        float acc = 0.f;
        #pragma unroll 8
        for (int d = 0; d < DOWN; d++)
            acc = fmaf(sA[n * DOWN + d], sW[d * HID + t], acc);
        out[(base + n) * HID + t] = acc;
    }
}

// ---------------- launch ---------------------------------------------------
extern "C" void kernel_launch(void* const* d_in, const int* in_sizes, int n_in,
                              void* d_out, int out_size) {
    const float* x      = (const float*)d_in[0];
    const float* robs   = (const float*)d_in[1];
    const float* shbs   = (const float*)d_in[2];
    const float* coeffs = (const float*)d_in[3];
    const int*   eidx   = (const int*)d_in[4];
    const int*   idx_j  = (const int*)d_in[5];
    const int*   idx_k  = (const int*)d_in[6];
    const int*   e_kj   = (const int*)d_in[7];
    const int*   e_ji   = (const int*)d_in[8];
    const float* Wn1    = (const float*)d_in[9];
    const float* bn1    = (const float*)d_in[10];
    const float* Wn2    = (const float*)d_in[11];
    const float* bn2    = (const float*)d_in[12];
    const float* Wc1    = (const float*)d_in[13];
    const float* Wc2    = (const float*)d_in[14];
    const float* Wup    = (const float*)d_in[15];
    float* out = (float*)d_out;

    // dynamic smem opt-in (idempotent, no static guards)
    cudaFuncSetAttribute(node_mlp_kernel, cudaFuncAttributeMaxDynamicSharedMemorySize, 21664 * 4);
    cudaFuncSetAttribute(co_mlp_kernel,   cudaFuncAttributeMaxDynamicSharedMemorySize, 16128 * 4);

    // zero tw + agg
    zero_all_kernel<<<100625, 256>>>();

    // node MLP: 20000/16 = 1250 blocks
    node_mlp_kernel<<<1250, 128, 21664 * 4>>>(x, Wn1, bn1, Wn2, bn2);

    // coeffs MLP: 320000/16 = 20000 blocks
    co_mlp_kernel<<<20000, 128, 16128 * 4>>>(coeffs, Wc1, Wc2);

    // triplet: 400000 warps, 8 warps/block
    triplet_kernel<<<N_TRIP / 8, 256>>>(robs, shbs, idx_j, idx_k, e_kj, e_ji);

    // edge: 200000 warps, 8 warps/block
    edge_kernel<<<N_EDGES / 8, 256>>>(robs, eidx);

    // up-projection: 20000/16 = 1250 blocks
    up_kernel<<<1250, 128>>>(Wup, out);
}

// round 2
// speedup vs baseline: 1.1331x; 1.1331x over previous
#include <cuda_runtime.h>

#define N_NODES 20000
#define N_EDGES 200000
#define N_TRIP  400000
#define HID 128
#define DOWN 32
#define CO 64
#define DR 16

// ---------------- device scratch (no allocations allowed) ----------------
__device__ float g_xd[N_NODES * DOWN];          // 2.56 MB
// blocked layout: c[node][rb][lane][ri]  (row r = rb*4+ri, lane = DOWN idx)
__device__ float g_c[N_NODES * DR * DOWN];      // 40.96 MB
__device__ float g_agg[N_NODES * DOWN];         // 2.56 MB
__device__ int   g_head[N_EDGES];               // per-edge triplet list head
__device__ int   g_next[N_TRIP];                // list links

__device__ __forceinline__ float silu_f(float v) {
    return v / (1.0f + __expf(-v));
}

__device__ __forceinline__ float warp_sum32(float s) {
    s += __shfl_xor_sync(0xffffffffu, s, 16);
    s += __shfl_xor_sync(0xffffffffu, s, 8);
    s += __shfl_xor_sync(0xffffffffu, s, 4);
    s += __shfl_xor_sync(0xffffffffu, s, 2);
    s += __shfl_xor_sync(0xffffffffu, s, 1);
    return s;
}

// ---------------- K0: init agg=0, head=-1 ---------------------------------
__global__ void init_kernel() {
    int i = blockIdx.x * blockDim.x + threadIdx.x;
    if (i < N_NODES * DOWN) g_agg[i] = 0.f;
    else {
        int h = i - N_NODES * DOWN;
        if (h < N_EDGES) g_head[h] = -1;
    }
}

// ---------------- K0b: build per-edge triplet linked lists ----------------
__global__ void build_list_kernel(const int* __restrict__ e_ji) {
    int i = blockIdx.x * blockDim.x + threadIdx.x;
    if (i >= N_TRIP) return;
    int ji = e_ji[i];
    g_next[i] = atomicExch(&g_head[ji], i);
}

// ---------------- K1: node MLP  x -> x_d [N,32] --------------------------
__global__ void node_mlp_kernel(const float* __restrict__ x,
                                const float* __restrict__ W1,
                                const float* __restrict__ b1,
                                const float* __restrict__ W2,
                                const float* __restrict__ b2) {
    extern __shared__ float sm[];
    float* sW1 = sm;              // 16384
    float* sW2 = sm + 16384;      // 4096
    float* sb1 = sm + 20480;      // 128
    float* sb2 = sm + 20608;      // 32
    float* h0  = sm + 20640;      // 512
    float* h1  = sm + 21152;      // 512

    int t = threadIdx.x;
    for (int i = t; i < 16384; i += 128) sW1[i] = W1[i];
    for (int i = t; i < 4096;  i += 128) sW2[i] = W2[i];
    if (t < 128) sb1[t] = b1[t];
    if (t < 32)  sb2[t] = b2[t];
    __syncthreads();

    int base = blockIdx.x * 16;
    for (int n0 = 0; n0 < 16; n0 += 4) {
        float4 hv;
        hv.x = silu_f(x[(base + n0 + 0) * HID + t]);
        hv.y = silu_f(x[(base + n0 + 1) * HID + t]);
        hv.z = silu_f(x[(base + n0 + 2) * HID + t]);
        hv.w = silu_f(x[(base + n0 + 3) * HID + t]);
        *reinterpret_cast<float4*>(&h0[t * 4]) = hv;
        __syncthreads();

        float4 acc = make_float4(sb1[t], sb1[t], sb1[t], sb1[t]);
        #pragma unroll 8
        for (int k = 0; k < 128; k++) {
            float w = sW1[k * 128 + t];
            float4 h = *reinterpret_cast<const float4*>(&h0[k * 4]);
            acc.x = fmaf(h.x, w, acc.x);
            acc.y = fmaf(h.y, w, acc.y);
            acc.z = fmaf(h.z, w, acc.z);
            acc.w = fmaf(h.w, w, acc.w);
        }
        float4 s1 = make_float4(silu_f(acc.x), silu_f(acc.y), silu_f(acc.z), silu_f(acc.w));
        *reinterpret_cast<float4*>(&h1[t * 4]) = s1;
        __syncthreads();

        if (t < 32) {
            float4 a2 = make_float4(sb2[t], sb2[t], sb2[t], sb2[t]);
            #pragma unroll 8
            for (int k = 0; k < 128; k++) {
                float w = sW2[k * 32 + t];
                float4 h = *reinterpret_cast<const float4*>(&h1[k * 4]);
                a2.x = fmaf(h.x, w, a2.x);
                a2.y = fmaf(h.y, w, a2.y);
                a2.z = fmaf(h.z, w, a2.z);
                a2.w = fmaf(h.w, w, a2.w);
            }
            g_xd[(base + n0 + 0) * DOWN + t] = a2.x;
            g_xd[(base + n0 + 1) * DOWN + t] = a2.y;
            g_xd[(base + n0 + 2) * DOWN + t] = a2.z;
            g_xd[(base + n0 + 3) * DOWN + t] = a2.w;
        }
        __syncthreads();
    }
}

// ---------------- K2: coeffs MLP -> blocked c ------------------------------
// block = 128 threads handles one node (16 DR rows)
#define H0S 20
#define H1S 20
__global__ void co_mlp_kernel(const float* __restrict__ cin,
                              const float* __restrict__ W1,
                              const float* __restrict__ W2) {
    extern __shared__ float sm[];
    float* sW1 = sm;              // 8192
    float* sW2 = sm + 8192;       // 4096
    float* h0  = sm + 12288;      // 64*20
    float* h1  = sm + 13568;      // 128*20

    int t = threadIdx.x;
    for (int i = t; i < 8192; i += 128) sW1[i] = W1[i];
    for (int i = t; i < 4096; i += 128) sW2[i] = W2[i];

    int node = blockIdx.x;
    int baserow = node * 16;
    for (int i = t; i < 1024; i += 128) {
        int rr = i >> 6, k = i & 63;
        h0[k * H0S + rr] = silu_f(cin[(baserow + rr) * CO + k]);
    }
    __syncthreads();

    for (int c = 0; c < 4; c++) {
        float4 acc = make_float4(0.f, 0.f, 0.f, 0.f);
        #pragma unroll 8
        for (int k = 0; k < 64; k++) {
            float w = sW1[k * 128 + t];
            float4 h = *reinterpret_cast<const float4*>(&h0[k * H0S + c * 4]);
            acc.x = fmaf(h.x, w, acc.x);
            acc.y = fmaf(h.y, w, acc.y);
            acc.z = fmaf(h.z, w, acc.z);
            acc.w = fmaf(h.w, w, acc.w);
        }
        float4 s = make_float4(silu_f(acc.x), silu_f(acc.y), silu_f(acc.z), silu_f(acc.w));
        *reinterpret_cast<float4*>(&h1[t * H1S + c * 4]) = s;
    }
    __syncthreads();

    // layer 2: warp g handles rows g*4..g*4+3 (= block rb=g, ri=0..3), lane = out col
    int g = t >> 5, j = t & 31;
    float4 acc = make_float4(0.f, 0.f, 0.f, 0.f);
    #pragma unroll 8
    for (int k = 0; k < 128; k++) {
        float w = sW2[k * 32 + j];
        float4 h = *reinterpret_cast<const float4*>(&h1[k * H1S + g * 4]);
        acc.x = fmaf(h.x, w, acc.x);
        acc.y = fmaf(h.y, w, acc.y);
        acc.z = fmaf(h.z, w, acc.z);
        acc.w = fmaf(h.w, w, acc.w);
    }
    // blocked store: c[node][rb=g][lane=j][ri] — coalesced float4
    *reinterpret_cast<float4*>(&g_c[node * 512 + g * 128 + j * 4]) = acc;
}

// ---------------- K3: fused triplet + edge + aggregation ------------------
// warp per edge; lane = DOWN index. tw kept in registers.
__global__ void fused_edge_kernel(const float* __restrict__ robs,
                                  const float* __restrict__ shbs,
                                  const int* __restrict__ idx_j,
                                  const int* __restrict__ idx_k,
                                  const int* __restrict__ e_kj,
                                  const int* __restrict__ edge_index) {
    int e    = (blockIdx.x * blockDim.x + threadIdx.x) >> 5;
    int lane = threadIdx.x & 31;
    if (e >= N_EDGES) return;

    const float4* c4 = reinterpret_cast<const float4*>(g_c);

    float4 tw[4];
    #pragma unroll
    for (int rb = 0; rb < 4; rb++) tw[rb] = make_float4(0.f, 0.f, 0.f, 0.f);

    // -------- accumulate tw over this edge's triplets --------
    int t = g_head[e];
    while (t != -1) {
        int j  = idx_j[t];
        int k  = idx_k[t];
        int kj = e_kj[t];

        float wl = 0.f;
        if (lane < DR) wl = shbs[t * DR + lane] * robs[kj * DR + lane];

        #pragma unroll
        for (int rb = 0; rb < 4; rb++) {
            float4 a = c4[k * 128 + rb * 32 + lane];   // rows rb*4..rb*4+3
            float4 b = c4[j * 128 + rb * 32 + lane];
            float4 v;
            v.x = fmaf(a.x, b.x, a.x);
            v.y = fmaf(a.y, b.y, a.y);
            v.z = fmaf(a.z, b.z, a.z);
            v.w = fmaf(a.w, b.w, a.w);

            float sx = warp_sum32(v.x * v.x);
            float sy = warp_sum32(v.y * v.y);
            float sz = warp_sum32(v.z * v.z);
            float sw = warp_sum32(v.w * v.w);

            float w0 = __shfl_sync(0xffffffffu, wl, rb * 4 + 0);
            float w1 = __shfl_sync(0xffffffffu, wl, rb * 4 + 1);
            float w2 = __shfl_sync(0xffffffffu, wl, rb * 4 + 2);
            float w3 = __shfl_sync(0xffffffffu, wl, rb * 4 + 3);

            tw[rb].x = fmaf(v.x, w0 / fmaxf(sqrtf(sx), 1e-12f), tw[rb].x);
            tw[rb].y = fmaf(v.y, w1 / fmaxf(sqrtf(sy), 1e-12f), tw[rb].y);
            tw[rb].z = fmaf(v.z, w2 / fmaxf(sqrtf(sz), 1e-12f), tw[rb].z);
            tw[rb].w = fmaf(v.w, w3 / fmaxf(sqrtf(sw), 1e-12f), tw[rb].w);
        }
        t = g_next[t];
    }

    // -------- edge interaction --------
    int src = edge_index[e];              // edge_index[0]
    int dst = edge_index[N_EDGES + e];    // edge_index[1]

    float rl = (lane < DR) ? robs[e * DR + lane] : 0.f;

    float acc = 0.f;
    #pragma unroll
    for (int rb = 0; rb < 4; rb++) {
        float4 a = c4[dst * 128 + rb * 32 + lane];
        float4 b = c4[src * 128 + rb * 32 + lane];
        float4 v;
        v.x = fmaf(a.x, b.x, a.x) * tw[rb].x;
        v.y = fmaf(a.y, b.y, a.y) * tw[rb].y;
        v.z = fmaf(a.z, b.z, a.z) * tw[rb].z;
        v.w = fmaf(a.w, b.w, a.w) * tw[rb].w;

        float sx = warp_sum32(v.x * v.x);
        float sy = warp_sum32(v.y * v.y);
        float sz = warp_sum32(v.z * v.z);
        float sw = warp_sum32(v.w * v.w);

        float w0 = __shfl_sync(0xffffffffu, rl, rb * 4 + 0);
        float w1 = __shfl_sync(0xffffffffu, rl, rb * 4 + 1);
        float w2 = __shfl_sync(0xffffffffu, rl, rb * 4 + 2);
        float w3 = __shfl_sync(0xffffffffu, rl, rb * 4 + 3);

        acc = fmaf(w0, v.x / fmaxf(sqrtf(sx), 1e-12f), acc);
        acc = fmaf(w1, v.y / fmaxf(sqrtf(sy), 1e-12f), acc);
        acc = fmaf(w2, v.z / fmaxf(sqrtf(sz), 1e-12f), acc);
        acc = fmaf(w3, v.w / fmaxf(sqrtf(sw), 1e-12f), acc);
    }

    float s2 = warp_sum32(acc * acc);
    float rd = acc / fmaxf(sqrtf(s2), 1e-12f);

    atomicAdd(&g_agg[src * DOWN + lane], g_xd[dst * DOWN + lane] * rd);
}

// ---------------- K5: up-projection ---------------------------------------
__global__ void up_kernel(const float* __restrict__ Wup,
                          float* __restrict__ out) {
    __shared__ float sW[DOWN * HID];
    __shared__ float sA[16 * DOWN];
    int t = threadIdx.x;
    for (int i = t; i < DOWN * HID; i += 128) sW[i] = Wup[i];
    int base = blockIdx.x * 16;
    for (int i = t; i < 512; i += 128) sA[i] = g_agg[base * DOWN + i];
    __syncthreads();

    for (int n = 0; n < 16; n++) {
        float acc = 0.f;
        #pragma unroll 8
        for (int d = 0; d < DOWN; d++)
            acc = fmaf(sA[n * DOWN + d], sW[d * HID + t], acc);
        out[(base + n) * HID + t] = acc;
    }
}

// ---------------- launch ---------------------------------------------------
extern "C" void kernel_launch(void* const* d_in, const int* in_sizes, int n_in,
                              void* d_out, int out_size) {
    const float* x      = (const float*)d_in[0];
    const float* robs   = (const float*)d_in[1];
    const float* shbs   = (const float*)d_in[2];
    const float* coeffs = (const float*)d_in[3];
    const int*   eidx   = (const int*)d_in[4];
    const int*   idx_j  = (const int*)d_in[5];
    const int*   idx_k  = (const int*)d_in[6];
    const int*   e_kj   = (const int*)d_in[7];
    const int*   e_ji   = (const int*)d_in[8];
    const float* Wn1    = (const float*)d_in[9];
    const float* bn1    = (const float*)d_in[10];
    const float* Wn2    = (const float*)d_in[11];
    const float* bn2    = (const float*)d_in[12];
    const float* Wc1    = (const float*)d_in[13];
    const float* Wc2    = (const float*)d_in[14];
    const float* Wup    = (const float*)d_in[15];
    float* out = (float*)d_out;

    cudaFuncSetAttribute(node_mlp_kernel, cudaFuncAttributeMaxDynamicSharedMemorySize, 21664 * 4);
    cudaFuncSetAttribute(co_mlp_kernel,   cudaFuncAttributeMaxDynamicSharedMemorySize, 16128 * 4);

    // init agg + list heads: 640000 + 200000 = 840000 threads
    init_kernel<<<(840000 + 255) / 256, 256>>>();

    // build per-edge triplet lists
    build_list_kernel<<<(N_TRIP + 255) / 256, 256>>>(e_ji);

    // node MLP
    node_mlp_kernel<<<1250, 128, 21664 * 4>>>(x, Wn1, bn1, Wn2, bn2);

    // coeffs MLP (one node per block)
    co_mlp_kernel<<<N_NODES, 128, 16128 * 4>>>(coeffs, Wc1, Wc2);

    // fused triplet + edge + aggregation: warp per edge
    fused_edge_kernel<<<N_EDGES / 8, 256>>>(robs, shbs, idx_j, idx_k, e_kj, eidx);

    // up-projection
    up_kernel<<<1250, 128>>>(Wup, out);
}

// round 3
// speedup vs baseline: 1.6156x; 1.4258x over previous
#include <cuda_runtime.h>

#define N_NODES 20000
#define N_EDGES 200000
#define N_TRIP  400000
#define HID 128
#define DOWN 32
#define CO 64
#define DR 16

// ---------------- device scratch (no allocations allowed) ----------------
__device__ float g_xd[N_NODES * DOWN];          // 2.56 MB
// blocked layout: c[node][rb][lane][ri]  (row r = rb*4+ri, lane = DOWN idx)
__device__ float g_c[N_NODES * DR * DOWN];      // 40.96 MB
__device__ float g_agg[N_NODES * DOWN];         // 2.56 MB
__device__ int   g_head[N_EDGES];               // per-edge triplet list head
__device__ int   g_next[N_TRIP];                // list links

__device__ __forceinline__ float silu_f(float v) {
    return v / (1.0f + __expf(-v));
}

__device__ __forceinline__ float warp_sum32(float s) {
    s += __shfl_xor_sync(0xffffffffu, s, 16);
    s += __shfl_xor_sync(0xffffffffu, s, 8);
    s += __shfl_xor_sync(0xffffffffu, s, 4);
    s += __shfl_xor_sync(0xffffffffu, s, 2);
    s += __shfl_xor_sync(0xffffffffu, s, 1);
    return s;
}

// ---------------- K0: init agg=0, head=-1 ---------------------------------
__global__ void init_kernel() {
    int i = blockIdx.x * blockDim.x + threadIdx.x;
    if (i < N_NODES * DOWN) g_agg[i] = 0.f;
    else {
        int h = i - N_NODES * DOWN;
        if (h < N_EDGES) g_head[h] = -1;
    }
}

// ---------------- K0b: build per-edge triplet linked lists ----------------
__global__ void build_list_kernel(const int* __restrict__ e_ji) {
    int i = blockIdx.x * blockDim.x + threadIdx.x;
    if (i >= N_TRIP) return;
    int ji = e_ji[i];
    g_next[i] = atomicExch(&g_head[ji], i);
}

// ---------------- K1: node MLP  x -> x_d [N,32] --------------------------
__global__ void node_mlp_kernel(const float* __restrict__ x,
                                const float* __restrict__ W1,
                                const float* __restrict__ b1,
                                const float* __restrict__ W2,
                                const float* __restrict__ b2) {
    extern __shared__ float sm[];
    float* sW1 = sm;              // 16384
    float* sW2 = sm + 16384;      // 4096
    float* sb1 = sm + 20480;      // 128
    float* sb2 = sm + 20608;      // 32
    float* h0  = sm + 20640;      // 512
    float* h1  = sm + 21152;      // 512

    int t = threadIdx.x;
    for (int i = t; i < 16384; i += 128) sW1[i] = W1[i];
    for (int i = t; i < 4096;  i += 128) sW2[i] = W2[i];
    if (t < 128) sb1[t] = b1[t];
    if (t < 32)  sb2[t] = b2[t];
    __syncthreads();

    int base = blockIdx.x * 16;
    for (int n0 = 0; n0 < 16; n0 += 4) {
        float4 hv;
        hv.x = silu_f(x[(base + n0 + 0) * HID + t]);
        hv.y = silu_f(x[(base + n0 + 1) * HID + t]);
        hv.z = silu_f(x[(base + n0 + 2) * HID + t]);
        hv.w = silu_f(x[(base + n0 + 3) * HID + t]);
        *reinterpret_cast<float4*>(&h0[t * 4]) = hv;
        __syncthreads();

        float4 acc = make_float4(sb1[t], sb1[t], sb1[t], sb1[t]);
        #pragma unroll 8
        for (int k = 0; k < 128; k++) {
            float w = sW1[k * 128 + t];
            float4 h = *reinterpret_cast<const float4*>(&h0[k * 4]);
            acc.x = fmaf(h.x, w, acc.x);
            acc.y = fmaf(h.y, w, acc.y);
            acc.z = fmaf(h.z, w, acc.z);
            acc.w = fmaf(h.w, w, acc.w);
        }
        float4 s1 = make_float4(silu_f(acc.x), silu_f(acc.y), silu_f(acc.z), silu_f(acc.w));
        *reinterpret_cast<float4*>(&h1[t * 4]) = s1;
        __syncthreads();

        if (t < 32) {
            float4 a2 = make_float4(sb2[t], sb2[t], sb2[t], sb2[t]);
            #pragma unroll 8
            for (int k = 0; k < 128; k++) {
                float w = sW2[k * 32 + t];
                float4 h = *reinterpret_cast<const float4*>(&h1[k * 4]);
                a2.x = fmaf(h.x, w, a2.x);
                a2.y = fmaf(h.y, w, a2.y);
                a2.z = fmaf(h.z, w, a2.z);
                a2.w = fmaf(h.w, w, a2.w);
            }
            g_xd[(base + n0 + 0) * DOWN + t] = a2.x;
            g_xd[(base + n0 + 1) * DOWN + t] = a2.y;
            g_xd[(base + n0 + 2) * DOWN + t] = a2.z;
            g_xd[(base + n0 + 3) * DOWN + t] = a2.w;
        }
        __syncthreads();
    }
}

// ---------------- K2: coeffs MLP -> blocked c (register-tiled GEMM) -------
// 256 threads, 64 rows (4 nodes) per block; grid = 5000
// smem: sW1 8192 | sW2 4096 | sX [64k][64r] 4096 | sH [128k][68pad] 8704
#define CO_SMEM (8192 + 4096 + 4096 + 8704)
__global__ __launch_bounds__(256) void co_mlp_kernel(const float* __restrict__ cin,
                                                     const float* __restrict__ W1,
                                                     const float* __restrict__ W2) {
    extern __shared__ float sm[];
    float* sW1 = sm;                 // [k=64][col=128]
    float* sW2 = sm + 8192;          // [k=128][col=32]
    float* sX  = sm + 12288;         // [k=64][row=64]
    float* sH  = sm + 16384;         // [k=128][row pad 68]

    int tid = threadIdx.x;
    int rowbase = blockIdx.x * 64;

    // weights (L2-resident across blocks)
    #pragma unroll
    for (int i = tid; i < 2048; i += 256)
        reinterpret_cast<float4*>(sW1)[i] = reinterpret_cast<const float4*>(W1)[i];
    #pragma unroll
    for (int i = tid; i < 1024; i += 256)
        reinterpret_cast<float4*>(sW2)[i] = reinterpret_cast<const float4*>(W2)[i];

    // load X, silu, transpose into sX[k][row]
    {
        int r  = tid & 63;
        int kc = tid >> 6;   // 0..3, 16 k each
        const float4* cin4 = reinterpret_cast<const float4*>(cin + (size_t)(rowbase + r) * CO);
        #pragma unroll
        for (int m = 0; m < 4; m++) {
            float4 v = cin4[kc * 4 + m];
            int k0 = kc * 16 + m * 4;
            sX[(k0 + 0) * 64 + r] = silu_f(v.x);
            sX[(k0 + 1) * 64 + r] = silu_f(v.y);
            sX[(k0 + 2) * 64 + r] = silu_f(v.z);
            sX[(k0 + 3) * 64 + r] = silu_f(v.w);
        }
    }
    __syncthreads();

    int tr = tid & 15;    // row group (4 rows)
    int tc = tid >> 4;    // col group

    // -------- layer 1: 64 -> 128, thread tile 4x8 --------
    float acc[4][8];
    #pragma unroll
    for (int i = 0; i < 4; i++)
        #pragma unroll
        for (int j = 0; j < 8; j++) acc[i][j] = 0.f;

    const float4* sX4  = reinterpret_cast<const float4*>(sX);
    const float4* sW14 = reinterpret_cast<const float4*>(sW1);
    #pragma unroll 4
    for (int k = 0; k < 64; k++) {
        float4 a  = sX4[k * 16 + tr];
        float4 b0 = sW14[k * 32 + tc * 2];
        float4 b1 = sW14[k * 32 + tc * 2 + 1];
        float av[4] = {a.x, a.y, a.z, a.w};
        float bv[8] = {b0.x, b0.y, b0.z, b0.w, b1.x, b1.y, b1.z, b1.w};
        #pragma unroll
        for (int i = 0; i < 4; i++)
            #pragma unroll
            for (int j = 0; j < 8; j++)
                acc[i][j] = fmaf(av[i], bv[j], acc[i][j]);
    }

    // silu + transpose into sH[col][row] (stride 17 float4)
    float4* sH4 = reinterpret_cast<float4*>(sH);
    #pragma unroll
    for (int j = 0; j < 8; j++) {
        int col = tc * 8 + j;
        float4 v = make_float4(silu_f(acc[0][j]), silu_f(acc[1][j]),
                               silu_f(acc[2][j]), silu_f(acc[3][j]));
        sH4[col * 17 + tr] = v;
    }
    __syncthreads();

    // -------- layer 2: 128 -> 32, thread tile 4x2 --------
    float a20 = 0.f, a21 = 0.f, a22 = 0.f, a23 = 0.f;
    float a30 = 0.f, a31 = 0.f, a32 = 0.f, a33 = 0.f;
    const float2* sW22 = reinterpret_cast<const float2*>(sW2);
    #pragma unroll 8
    for (int k = 0; k < 128; k++) {
        float4 a = sH4[k * 17 + tr];
        float2 b = sW22[k * 16 + tc];
        a20 = fmaf(a.x, b.x, a20);
        a21 = fmaf(a.y, b.x, a21);
        a22 = fmaf(a.z, b.x, a22);
        a23 = fmaf(a.w, b.x, a23);
        a30 = fmaf(a.x, b.y, a30);
        a31 = fmaf(a.y, b.y, a31);
        a32 = fmaf(a.z, b.y, a32);
        a33 = fmaf(a.w, b.y, a33);
    }

    // store blocked: c[node][rb][lane][ri], node = grow/16, rb = (grow%16)/4
    int node = (rowbase >> 4) + (tr >> 2);
    int rb   = tr & 3;
    float4* out4 = reinterpret_cast<float4*>(g_c);
    out4[node * 128 + rb * 32 + tc * 2 + 0] = make_float4(a20, a21, a22, a23);
    out4[node * 128 + rb * 32 + tc * 2 + 1] = make_float4(a30, a31, a32, a33);
}

// ---------------- K3: fused triplet + edge + aggregation ------------------
__global__ void fused_edge_kernel(const float* __restrict__ robs,
                                  const float* __restrict__ shbs,
                                  const int* __restrict__ idx_j,
                                  const int* __restrict__ idx_k,
                                  const int* __restrict__ e_kj,
                                  const int* __restrict__ edge_index) {
    int e    = (blockIdx.x * blockDim.x + threadIdx.x) >> 5;
    int lane = threadIdx.x & 31;
    if (e >= N_EDGES) return;

    const float4* c4 = reinterpret_cast<const float4*>(g_c);

    float4 tw[4];
    #pragma unroll
    for (int rb = 0; rb < 4; rb++) tw[rb] = make_float4(0.f, 0.f, 0.f, 0.f);

    int t = g_head[e];
    while (t != -1) {
        int j  = idx_j[t];
        int k  = idx_k[t];
        int kj = e_kj[t];

        float wl = 0.f;
        if (lane < DR) wl = shbs[t * DR + lane] * robs[kj * DR + lane];

        #pragma unroll
        for (int rb = 0; rb < 4; rb++) {
            float4 a = c4[k * 128 + rb * 32 + lane];
            float4 b = c4[j * 128 + rb * 32 + lane];
            float4 v;
            v.x = fmaf(a.x, b.x, a.x);
            v.y = fmaf(a.y, b.y, a.y);
            v.z = fmaf(a.z, b.z, a.z);
            v.w = fmaf(a.w, b.w, a.w);

            float sx = warp_sum32(v.x * v.x);
            float sy = warp_sum32(v.y * v.y);
            float sz = warp_sum32(v.z * v.z);
            float sw = warp_sum32(v.w * v.w);

            float w0 = __shfl_sync(0xffffffffu, wl, rb * 4 + 0);
            float w1 = __shfl_sync(0xffffffffu, wl, rb * 4 + 1);
            float w2 = __shfl_sync(0xffffffffu, wl, rb * 4 + 2);
            float w3 = __shfl_sync(0xffffffffu, wl, rb * 4 + 3);

            tw[rb].x = fmaf(v.x, w0 / fmaxf(sqrtf(sx), 1e-12f), tw[rb].x);
            tw[rb].y = fmaf(v.y, w1 / fmaxf(sqrtf(sy), 1e-12f), tw[rb].y);
            tw[rb].z = fmaf(v.z, w2 / fmaxf(sqrtf(sz), 1e-12f), tw[rb].z);
            tw[rb].w = fmaf(v.w, w3 / fmaxf(sqrtf(sw), 1e-12f), tw[rb].w);
        }
        t = g_next[t];
    }

    int src = edge_index[e];
    int dst = edge_index[N_EDGES + e];

    float rl = (lane < DR) ? robs[e * DR + lane] : 0.f;

    float acc = 0.f;
    #pragma unroll
    for (int rb = 0; rb < 4; rb++) {
        float4 a = c4[dst * 128 + rb * 32 + lane];
        float4 b = c4[src * 128 + rb * 32 + lane];
        float4 v;
        v.x = fmaf(a.x, b.x, a.x) * tw[rb].x;
        v.y = fmaf(a.y, b.y, a.y) * tw[rb].y;
        v.z = fmaf(a.z, b.z, a.z) * tw[rb].z;
        v.w = fmaf(a.w, b.w, a.w) * tw[rb].w;

        float sx = warp_sum32(v.x * v.x);
        float sy = warp_sum32(v.y * v.y);
        float sz = warp_sum32(v.z * v.z);
        float sw = warp_sum32(v.w * v.w);

        float w0 = __shfl_sync(0xffffffffu, rl, rb * 4 + 0);
        float w1 = __shfl_sync(0xffffffffu, rl, rb * 4 + 1);
        float w2 = __shfl_sync(0xffffffffu, rl, rb * 4 + 2);
        float w3 = __shfl_sync(0xffffffffu, rl, rb * 4 + 3);

        acc = fmaf(w0, v.x / fmaxf(sqrtf(sx), 1e-12f), acc);
        acc = fmaf(w1, v.y / fmaxf(sqrtf(sy), 1e-12f), acc);
        acc = fmaf(w2, v.z / fmaxf(sqrtf(sz), 1e-12f), acc);
        acc = fmaf(w3, v.w / fmaxf(sqrtf(sw), 1e-12f), acc);
    }

    float s2 = warp_sum32(acc * acc);
    float rd = acc / fmaxf(sqrtf(s2), 1e-12f);

    atomicAdd(&g_agg[src * DOWN + lane], g_xd[dst * DOWN + lane] * rd);
}

// ---------------- K5: up-projection ---------------------------------------
__global__ void up_kernel(const float* __restrict__ Wup,
                          float* __restrict__ out) {
    __shared__ float sW[DOWN * HID];
    __shared__ float sA[16 * DOWN];
    int t = threadIdx.x;
    for (int i = t; i < DOWN * HID; i += 128) sW[i] = Wup[i];
    int base = blockIdx.x * 16;
    for (int i = t; i < 512; i += 128) sA[i] = g_agg[base * DOWN + i];
    __syncthreads();

    for (int n = 0; n < 16; n++) {
        float acc = 0.f;
        #pragma unroll 8
        for (int d = 0; d < DOWN; d++)
            acc = fmaf(sA[n * DOWN + d], sW[d * HID + t], acc);
        out[(base + n) * HID + t] = acc;
    }
}

// ---------------- launch ---------------------------------------------------
extern "C" void kernel_launch(void* const* d_in, const int* in_sizes, int n_in,
                              void* d_out, int out_size) {
    const float* x      = (const float*)d_in[0];
    const float* robs   = (const float*)d_in[1];
    const float* shbs   = (const float*)d_in[2];
    const float* coeffs = (const float*)d_in[3];
    const int*   eidx   = (const int*)d_in[4];
    const int*   idx_j  = (const int*)d_in[5];
    const int*   idx_k  = (const int*)d_in[6];
    const int*   e_kj   = (const int*)d_in[7];
    const int*   e_ji   = (const int*)d_in[8];
    const float* Wn1    = (const float*)d_in[9];
    const float* bn1    = (const float*)d_in[10];
    const float* Wn2    = (const float*)d_in[11];
    const float* bn2    = (const float*)d_in[12];
    const float* Wc1    = (const float*)d_in[13];
    const float* Wc2    = (const float*)d_in[14];
    const float* Wup    = (const float*)d_in[15];
    float* out = (float*)d_out;

    cudaFuncSetAttribute(node_mlp_kernel, cudaFuncAttributeMaxDynamicSharedMemorySize, 21664 * 4);
    cudaFuncSetAttribute(co_mlp_kernel,   cudaFuncAttributeMaxDynamicSharedMemorySize, CO_SMEM * 4);

    init_kernel<<<(840000 + 255) / 256, 256>>>();
    build_list_kernel<<<(N_TRIP + 255) / 256, 256>>>(e_ji);

    node_mlp_kernel<<<1250, 128, 21664 * 4>>>(x, Wn1, bn1, Wn2, bn2);

    // coeffs MLP: 64 rows per block, 320000/64 = 5000 blocks
    co_mlp_kernel<<<5000, 256, CO_SMEM * 4>>>(coeffs, Wc1, Wc2);

    fused_edge_kernel<<<N_EDGES / 8, 256>>>(robs, shbs, idx_j, idx_k, e_kj, eidx);

    up_kernel<<<1250, 128>>>(Wup, out);
}

// round 4
// speedup vs baseline: 2.0776x; 1.2860x over previous
#include <cuda_runtime.h>

#define N_NODES 20000
#define N_EDGES 200000
#define N_TRIP  400000
#define HID 128
#define DOWN 32
#define CO 64
#define DR 16

// ---------------- device scratch (no allocations allowed) ----------------
__device__ float g_xd[N_NODES * DOWN];          // 2.56 MB
// quarter-interleaved layout: float4 #(node*128 + i*32 + l) holds
// row r = l>>1, half = l&1, floats [(l&1)*16 + i*4 .. +4) of c[node]
__device__ float g_c[N_NODES * DR * DOWN];      // 40.96 MB
__device__ float g_agg[N_NODES * DOWN];         // 2.56 MB
__device__ int   g_head[N_EDGES];               // per-edge triplet list head
__device__ int   g_next[N_TRIP];                // list links

__device__ __forceinline__ float silu_f(float v) {
    return v / (1.0f + __expf(-v));
}

// ---------------- K0: init agg=0, head=-1 ---------------------------------
__global__ void init_kernel() {
    int i = blockIdx.x * blockDim.x + threadIdx.x;
    if (i < N_NODES * DOWN) g_agg[i] = 0.f;
    else {
        int h = i - N_NODES * DOWN;
        if (h < N_EDGES) g_head[h] = -1;
    }
}

// ---------------- K0b: build per-edge triplet linked lists ----------------
__global__ void build_list_kernel(const int* __restrict__ e_ji) {
    int i = blockIdx.x * blockDim.x + threadIdx.x;
    if (i >= N_TRIP) return;
    int ji = e_ji[i];
    g_next[i] = atomicExch(&g_head[ji], i);
}

// ---------------- K1: node MLP  x -> x_d [N,32] --------------------------
__global__ void node_mlp_kernel(const float* __restrict__ x,
                                const float* __restrict__ W1,
                                const float* __restrict__ b1,
                                const float* __restrict__ W2,
                                const float* __restrict__ b2) {
    extern __shared__ float sm[];
    float* sW1 = sm;              // 16384
    float* sW2 = sm + 16384;      // 4096
    float* sb1 = sm + 20480;      // 128
    float* sb2 = sm + 20608;      // 32
    float* h0  = sm + 20640;      // 512
    float* h1  = sm + 21152;      // 512

    int t = threadIdx.x;
    for (int i = t; i < 16384; i += 128) sW1[i] = W1[i];
    for (int i = t; i < 4096;  i += 128) sW2[i] = W2[i];
    if (t < 128) sb1[t] = b1[t];
    if (t < 32)  sb2[t] = b2[t];
    __syncthreads();

    int base = blockIdx.x * 16;
    for (int n0 = 0; n0 < 16; n0 += 4) {
        float4 hv;
        hv.x = silu_f(x[(base + n0 + 0) * HID + t]);
        hv.y = silu_f(x[(base + n0 + 1) * HID + t]);
        hv.z = silu_f(x[(base + n0 + 2) * HID + t]);
        hv.w = silu_f(x[(base + n0 + 3) * HID + t]);
        *reinterpret_cast<float4*>(&h0[t * 4]) = hv;
        __syncthreads();

        float4 acc = make_float4(sb1[t], sb1[t], sb1[t], sb1[t]);
        #pragma unroll 8
        for (int k = 0; k < 128; k++) {
            float w = sW1[k * 128 + t];
            float4 h = *reinterpret_cast<const float4*>(&h0[k * 4]);
            acc.x = fmaf(h.x, w, acc.x);
            acc.y = fmaf(h.y, w, acc.y);
            acc.z = fmaf(h.z, w, acc.z);
            acc.w = fmaf(h.w, w, acc.w);
        }
        float4 s1 = make_float4(silu_f(acc.x), silu_f(acc.y), silu_f(acc.z), silu_f(acc.w));
        *reinterpret_cast<float4*>(&h1[t * 4]) = s1;
        __syncthreads();

        if (t < 32) {
            float4 a2 = make_float4(sb2[t], sb2[t], sb2[t], sb2[t]);
            #pragma unroll 8
            for (int k = 0; k < 128; k++) {
                float w = sW2[k * 32 + t];
                float4 h = *reinterpret_cast<const float4*>(&h1[k * 4]);
                a2.x = fmaf(h.x, w, a2.x);
                a2.y = fmaf(h.y, w, a2.y);
                a2.z = fmaf(h.z, w, a2.z);
                a2.w = fmaf(h.w, w, a2.w);
            }
            g_xd[(base + n0 + 0) * DOWN + t] = a2.x;
            g_xd[(base + n0 + 1) * DOWN + t] = a2.y;
            g_xd[(base + n0 + 2) * DOWN + t] = a2.z;
            g_xd[(base + n0 + 3) * DOWN + t] = a2.w;
        }
        __syncthreads();
    }
}

// ---------------- K2: coeffs MLP -> interleaved c (register-tiled GEMM) ---
// 256 threads, 64 rows (4 nodes) per block; grid = 5000
#define CO_SMEM (8192 + 4096 + 4096 + 8704)
__global__ __launch_bounds__(256) void co_mlp_kernel(const float* __restrict__ cin,
                                                     const float* __restrict__ W1,
                                                     const float* __restrict__ W2) {
    extern __shared__ float sm[];
    float* sW1 = sm;                 // [k=64][col=128]
    float* sW2 = sm + 8192;          // [k=128][col=32]
    float* sX  = sm + 12288;         // [k=64][row=64]; reused as sOut staging
    float* sH  = sm + 16384;         // [k=128][row pad 68]

    int tid = threadIdx.x;
    int rowbase = blockIdx.x * 64;

    #pragma unroll
    for (int i = tid; i < 2048; i += 256)
        reinterpret_cast<float4*>(sW1)[i] = reinterpret_cast<const float4*>(W1)[i];
    #pragma unroll
    for (int i = tid; i < 1024; i += 256)
        reinterpret_cast<float4*>(sW2)[i] = reinterpret_cast<const float4*>(W2)[i];

    // load X, silu, transpose into sX[k][row]
    {
        int r  = tid & 63;
        int kc = tid >> 6;
        const float4* cin4 = reinterpret_cast<const float4*>(cin + (size_t)(rowbase + r) * CO);
        #pragma unroll
        for (int m = 0; m < 4; m++) {
            float4 v = cin4[kc * 4 + m];
            int k0 = kc * 16 + m * 4;
            sX[(k0 + 0) * 64 + r] = silu_f(v.x);
            sX[(k0 + 1) * 64 + r] = silu_f(v.y);
            sX[(k0 + 2) * 64 + r] = silu_f(v.z);
            sX[(k0 + 3) * 64 + r] = silu_f(v.w);
        }
    }
    __syncthreads();

    int tr = tid & 15;    // row group (4 rows)
    int tc = tid >> 4;    // col group

    // -------- layer 1: 64 -> 128, thread tile 4x8 --------
    float acc[4][8];
    #pragma unroll
    for (int i = 0; i < 4; i++)
        #pragma unroll
        for (int j = 0; j < 8; j++) acc[i][j] = 0.f;

    const float4* sX4  = reinterpret_cast<const float4*>(sX);
    const float4* sW14 = reinterpret_cast<const float4*>(sW1);
    #pragma unroll 4
    for (int k = 0; k < 64; k++) {
        float4 a  = sX4[k * 16 + tr];
        float4 b0 = sW14[k * 32 + tc * 2];
        float4 b1 = sW14[k * 32 + tc * 2 + 1];
        float av[4] = {a.x, a.y, a.z, a.w};
        float bv[8] = {b0.x, b0.y, b0.z, b0.w, b1.x, b1.y, b1.z, b1.w};
        #pragma unroll
        for (int i = 0; i < 4; i++)
            #pragma unroll
            for (int j = 0; j < 8; j++)
                acc[i][j] = fmaf(av[i], bv[j], acc[i][j]);
    }

    // silu + transpose into sH[col][row] (stride 17 float4)
    float4* sH4 = reinterpret_cast<float4*>(sH);
    #pragma unroll
    for (int j = 0; j < 8; j++) {
        int col = tc * 8 + j;
        float4 v = make_float4(silu_f(acc[0][j]), silu_f(acc[1][j]),
                               silu_f(acc[2][j]), silu_f(acc[3][j]));
        sH4[col * 17 + tr] = v;
    }
    __syncthreads();

    // -------- layer 2: 128 -> 32, thread tile 4x2 --------
    float a20 = 0.f, a21 = 0.f, a22 = 0.f, a23 = 0.f;
    float a30 = 0.f, a31 = 0.f, a32 = 0.f, a33 = 0.f;
    const float2* sW22 = reinterpret_cast<const float2*>(sW2);
    #pragma unroll 8
    for (int k = 0; k < 128; k++) {
        float4 a = sH4[k * 17 + tr];
        float2 b = sW22[k * 16 + tc];
        a20 = fmaf(a.x, b.x, a20);
        a21 = fmaf(a.y, b.x, a21);
        a22 = fmaf(a.z, b.x, a22);
        a23 = fmaf(a.w, b.x, a23);
        a30 = fmaf(a.x, b.y, a30);
        a31 = fmaf(a.y, b.y, a31);
        a32 = fmaf(a.z, b.y, a32);
        a33 = fmaf(a.w, b.y, a33);
    }

    // -------- epilogue: stage rows in smem, write interleaved layout ------
    float* sOut = sX;   // 64 rows x 32 cols = 8KB (sX is dead now)
    int r0 = tr * 4;
    int c0 = tc * 2;
    sOut[(r0 + 0) * 32 + c0]     = a20;
    sOut[(r0 + 1) * 32 + c0]     = a21;
    sOut[(r0 + 2) * 32 + c0]     = a22;
    sOut[(r0 + 3) * 32 + c0]     = a23;
    sOut[(r0 + 0) * 32 + c0 + 1] = a30;
    sOut[(r0 + 1) * 32 + c0 + 1] = a31;
    sOut[(r0 + 2) * 32 + c0 + 1] = a32;
    sOut[(r0 + 3) * 32 + c0 + 1] = a33;
    __syncthreads();

    const float4* sOut4 = reinterpret_cast<const float4*>(sOut);
    float4* out4 = reinterpret_cast<float4*>(g_c);
    int nodebase = blockIdx.x * 4;
    #pragma unroll
    for (int mm = 0; mm < 2; mm++) {
        int m  = tid + mm * 256;        // 0..511
        int q  = m >> 7;                // node within block
        int w  = m & 127;               // float4 within node
        int i  = w >> 5;                // quarter
        int l  = w & 31;                // chunk lane
        int rr = l >> 1;
        int hf = l & 1;
        float4 vv = sOut4[(q * 16 + rr) * 8 + hf * 4 + i];
        out4[(size_t)(nodebase + q) * 128 + w] = vv;
    }
}

// ---------------- K3: fused triplet + edge + aggregation ------------------
// warp per edge; lane pair (2r, 2r+1) owns DR row r (16 h-values each).
__global__ __launch_bounds__(256) void fused_edge_kernel(
    const float* __restrict__ robs,
    const float* __restrict__ shbs,
    const int* __restrict__ idx_j,
    const int* __restrict__ idx_k,
    const int* __restrict__ e_kj,
    const int* __restrict__ edge_index) {
    int e    = (blockIdx.x * blockDim.x + threadIdx.x) >> 5;
    int lane = threadIdx.x & 31;
    if (e >= N_EDGES) return;

    const float4* c4 = reinterpret_cast<const float4*>(g_c);
    int hr = lane >> 1;                 // row this lane pair owns

    float tw[16];
    #pragma unroll
    for (int i = 0; i < 16; i++) tw[i] = 0.f;

    // -------- accumulate tw over this edge's triplets --------
    for (int t = g_head[e]; t != -1; t = g_next[t]) {
        int j  = idx_j[t];
        int k  = idx_k[t];
        int kj = e_kj[t];
        float w = shbs[t * DR + hr] * robs[kj * DR + hr];

        float v[16];
        #pragma unroll
        for (int i = 0; i < 4; i++) {
            float4 a = c4[(size_t)k * 128 + i * 32 + lane];
            float4 b = c4[(size_t)j * 128 + i * 32 + lane];
            v[i*4+0] = fmaf(a.x, b.x, a.x);
            v[i*4+1] = fmaf(a.y, b.y, a.y);
            v[i*4+2] = fmaf(a.z, b.z, a.z);
            v[i*4+3] = fmaf(a.w, b.w, a.w);
        }
        float p0 = 0.f, p1 = 0.f, p2 = 0.f, p3 = 0.f;
        #pragma unroll
        for (int i = 0; i < 4; i++) {
            p0 = fmaf(v[i*4+0], v[i*4+0], p0);
            p1 = fmaf(v[i*4+1], v[i*4+1], p1);
            p2 = fmaf(v[i*4+2], v[i*4+2], p2);
            p3 = fmaf(v[i*4+3], v[i*4+3], p3);
        }
        float ss = (p0 + p1) + (p2 + p3);
        ss += __shfl_xor_sync(0xffffffffu, ss, 1);   // full row norm
        float scale = w / fmaxf(sqrtf(ss), 1e-12f);
        #pragma unroll
        for (int i = 0; i < 16; i++) tw[i] = fmaf(scale, v[i], tw[i]);
    }

    // -------- edge interaction --------
    int src = edge_index[e];
    int dst = edge_index[N_EDGES + e];
    float wr = robs[e * DR + hr];

    float val[16];
    #pragma unroll
    for (int i = 0; i < 4; i++) {
        float4 a = c4[(size_t)dst * 128 + i * 32 + lane];
        float4 b = c4[(size_t)src * 128 + i * 32 + lane];
        val[i*4+0] = fmaf(a.x, b.x, a.x) * tw[i*4+0];
        val[i*4+1] = fmaf(a.y, b.y, a.y) * tw[i*4+1];
        val[i*4+2] = fmaf(a.z, b.z, a.z) * tw[i*4+2];
        val[i*4+3] = fmaf(a.w, b.w, a.w) * tw[i*4+3];
    }
    float p0 = 0.f, p1 = 0.f, p2 = 0.f, p3 = 0.f;
    #pragma unroll
    for (int i = 0; i < 4; i++) {
        p0 = fmaf(val[i*4+0], val[i*4+0], p0);
        p1 = fmaf(val[i*4+1], val[i*4+1], p1);
        p2 = fmaf(val[i*4+2], val[i*4+2], p2);
        p3 = fmaf(val[i*4+3], val[i*4+3], p3);
    }
    float ss = (p0 + p1) + (p2 + p3);
    ss += __shfl_xor_sync(0xffffffffu, ss, 1);
    float factor = wr / fmaxf(sqrtf(ss), 1e-12f);    // robs_r / ||v_r||
    #pragma unroll
    for (int i = 0; i < 16; i++) val[i] *= factor;

    // -------- fold: sum over the 16 rows (same-parity lanes) --------
    // stage s: if (lane & s) keep upper half (accumulating partner's upper)
    #pragma unroll
    for (int st = 0; st < 4; st++) {
        const int s  = 2 << st;       // 2,4,8,16
        const int n2 = 8 >> st;       // 8,4,2,1
        bool up = (lane & s) != 0;
        #pragma unroll
        for (int m = 0; m < n2; m++) {
            float send = up ? val[m] : val[m + n2];
            float recv = __shfl_xor_sync(0xffffffffu, send, s);
            val[m] = (up ? val[m + n2] : val[m]) + recv;
        }
    }
    float acc = val[0];
    // h index this lane ended up owning
    int idx = ((lane >> 1) & 1) * 8 + ((lane >> 2) & 1) * 4 +
              ((lane >> 3) & 1) * 2 + ((lane >> 4) & 1);
    int h = (lane & 1) * 16 + idx;

    // normalize r over h (full-warp butterfly)
    float sq = acc * acc;
    #pragma unroll
    for (int m = 1; m < 32; m <<= 1) sq += __shfl_xor_sync(0xffffffffu, sq, m);
    float rd = acc / fmaxf(sqrtf(sq), 1e-12f);

    atomicAdd(&g_agg[src * DOWN + h], g_xd[dst * DOWN + h] * rd);
}

// ---------------- K5: up-projection ---------------------------------------
__global__ void up_kernel(const float* __restrict__ Wup,
                          float* __restrict__ out) {
    __shared__ float sW[DOWN * HID];
    __shared__ float sA[16 * DOWN];
    int t = threadIdx.x;
    for (int i = t; i < DOWN * HID; i += 128) sW[i] = Wup[i];
    int base = blockIdx.x * 16;
    for (int i = t; i < 512; i += 128) sA[i] = g_agg[base * DOWN + i];
    __syncthreads();

    for (int n = 0; n < 16; n++) {
        float acc = 0.f;
        #pragma unroll 8
        for (int d = 0; d < DOWN; d++)
            acc = fmaf(sA[n * DOWN + d], sW[d * HID + t], acc);
        out[(base + n) * HID + t] = acc;
    }
}

// ---------------- launch ---------------------------------------------------
extern "C" void kernel_launch(void* const* d_in, const int* in_sizes, int n_in,
                              void* d_out, int out_size) {
    const float* x      = (const float*)d_in[0];
    const float* robs   = (const float*)d_in[1];
    const float* shbs   = (const float*)d_in[2];
    const float* coeffs = (const float*)d_in[3];
    const int*   eidx   = (const int*)d_in[4];
    const int*   idx_j  = (const int*)d_in[5];
    const int*   idx_k  = (const int*)d_in[6];
    const int*   e_kj   = (const int*)d_in[7];
    const int*   e_ji   = (const int*)d_in[8];
    const float* Wn1    = (const float*)d_in[9];
    const float* bn1    = (const float*)d_in[10];
    const float* Wn2    = (const float*)d_in[11];
    const float* bn2    = (const float*)d_in[12];
    const float* Wc1    = (const float*)d_in[13];
    const float* Wc2    = (const float*)d_in[14];
    const float* Wup    = (const float*)d_in[15];
    float* out = (float*)d_out;

    cudaFuncSetAttribute(node_mlp_kernel, cudaFuncAttributeMaxDynamicSharedMemorySize, 21664 * 4);
    cudaFuncSetAttribute(co_mlp_kernel,   cudaFuncAttributeMaxDynamicSharedMemorySize, CO_SMEM * 4);

    init_kernel<<<(840000 + 255) / 256, 256>>>();
    build_list_kernel<<<(N_TRIP + 255) / 256, 256>>>(e_ji);

    node_mlp_kernel<<<1250, 128, 21664 * 4>>>(x, Wn1, bn1, Wn2, bn2);

    co_mlp_kernel<<<5000, 256, CO_SMEM * 4>>>(coeffs, Wc1, Wc2);

    fused_edge_kernel<<<N_EDGES / 8, 256>>>(robs, shbs, idx_j, idx_k, e_kj, eidx);

    up_kernel<<<1250, 128>>>(Wup, out);
}

// round 5
// speedup vs baseline: 2.2216x; 1.0693x over previous
#include <cuda_runtime.h>

#define N_NODES 20000
#define N_EDGES 200000
#define N_TRIP  400000
#define HID 128
#define DOWN 32
#define CO 64
#define DR 16
#define SLOT_CAP 32

// ---------------- device scratch (no allocations allowed) ----------------
__device__ float g_xd[N_NODES * DOWN];          // 2.56 MB
// quarter-interleaved layout: float4 #(node*128 + i*32 + l) holds
// row r = l>>1, half = l&1, floats [(l&1)*16 + i*4 .. +4) of c[node]
__device__ float g_c[N_NODES * DR * DOWN];      // 40.96 MB
__device__ float g_agg[N_NODES * DOWN];         // 2.56 MB
__device__ int   g_cnt[N_EDGES];                // per-edge triplet count
__device__ int   g_slot[N_EDGES * SLOT_CAP];    // slotted CSR (25.6 MB)

__device__ __forceinline__ float silu_f(float v) {
    return v / (1.0f + __expf(-v));
}

// ---------------- K0: init agg=0, cnt=0 ------------------------------------
__global__ void init_kernel() {
    int i = blockIdx.x * blockDim.x + threadIdx.x;
    if (i < N_NODES * DOWN) g_agg[i] = 0.f;
    else {
        int h = i - N_NODES * DOWN;
        if (h < N_EDGES) g_cnt[h] = 0;
    }
}

// ---------------- K0b: fill slotted CSR -------------------------------------
__global__ void fill_kernel(const int* __restrict__ e_ji) {
    int i = blockIdx.x * blockDim.x + threadIdx.x;
    if (i >= N_TRIP) return;
    int ji = e_ji[i];
    int p = atomicAdd(&g_cnt[ji], 1);
    if (p < SLOT_CAP) g_slot[ji * SLOT_CAP + p] = i;
}

// ---------------- K1: node MLP  x -> x_d [N,32] --------------------------
__global__ void node_mlp_kernel(const float* __restrict__ x,
                                const float* __restrict__ W1,
                                const float* __restrict__ b1,
                                const float* __restrict__ W2,
                                const float* __restrict__ b2) {
    extern __shared__ float sm[];
    float* sW1 = sm;              // 16384
    float* sW2 = sm + 16384;      // 4096
    float* sb1 = sm + 20480;      // 128
    float* sb2 = sm + 20608;      // 32
    float* h0  = sm + 20640;      // 512
    float* h1  = sm + 21152;      // 512

    int t = threadIdx.x;
    for (int i = t; i < 16384; i += 128) sW1[i] = W1[i];
    for (int i = t; i < 4096;  i += 128) sW2[i] = W2[i];
    if (t < 128) sb1[t] = b1[t];
    if (t < 32)  sb2[t] = b2[t];
    __syncthreads();

    int base = blockIdx.x * 16;
    for (int n0 = 0; n0 < 16; n0 += 4) {
        float4 hv;
        hv.x = silu_f(x[(base + n0 + 0) * HID + t]);
        hv.y = silu_f(x[(base + n0 + 1) * HID + t]);
        hv.z = silu_f(x[(base + n0 + 2) * HID + t]);
        hv.w = silu_f(x[(base + n0 + 3) * HID + t]);
        *reinterpret_cast<float4*>(&h0[t * 4]) = hv;
        __syncthreads();

        float4 acc = make_float4(sb1[t], sb1[t], sb1[t], sb1[t]);
        #pragma unroll 8
        for (int k = 0; k < 128; k++) {
            float w = sW1[k * 128 + t];
            float4 h = *reinterpret_cast<const float4*>(&h0[k * 4]);
            acc.x = fmaf(h.x, w, acc.x);
            acc.y = fmaf(h.y, w, acc.y);
            acc.z = fmaf(h.z, w, acc.z);
            acc.w = fmaf(h.w, w, acc.w);
        }
        float4 s1 = make_float4(silu_f(acc.x), silu_f(acc.y), silu_f(acc.z), silu_f(acc.w));
        *reinterpret_cast<float4*>(&h1[t * 4]) = s1;
        __syncthreads();

        if (t < 32) {
            float4 a2 = make_float4(sb2[t], sb2[t], sb2[t], sb2[t]);
            #pragma unroll 8
            for (int k = 0; k < 128; k++) {
                float w = sW2[k * 32 + t];
                float4 h = *reinterpret_cast<const float4*>(&h1[k * 4]);
                a2.x = fmaf(h.x, w, a2.x);
                a2.y = fmaf(h.y, w, a2.y);
                a2.z = fmaf(h.z, w, a2.z);
                a2.w = fmaf(h.w, w, a2.w);
            }
            g_xd[(base + n0 + 0) * DOWN + t] = a2.x;
            g_xd[(base + n0 + 1) * DOWN + t] = a2.y;
            g_xd[(base + n0 + 2) * DOWN + t] = a2.z;
            g_xd[(base + n0 + 3) * DOWN + t] = a2.w;
        }
        __syncthreads();
    }
}

// ---------------- K2: coeffs MLP -> interleaved c (register-tiled GEMM) ---
#define CO_SMEM (8192 + 4096 + 4096 + 8704)
__global__ __launch_bounds__(256) void co_mlp_kernel(const float* __restrict__ cin,
                                                     const float* __restrict__ W1,
                                                     const float* __restrict__ W2) {
    extern __shared__ float sm[];
    float* sW1 = sm;                 // [k=64][col=128]
    float* sW2 = sm + 8192;          // [k=128][col=32]
    float* sX  = sm + 12288;         // [k=64][row=64]; reused as sOut staging
    float* sH  = sm + 16384;         // [k=128][row pad 68]

    int tid = threadIdx.x;
    int rowbase = blockIdx.x * 64;

    #pragma unroll
    for (int i = tid; i < 2048; i += 256)
        reinterpret_cast<float4*>(sW1)[i] = reinterpret_cast<const float4*>(W1)[i];
    #pragma unroll
    for (int i = tid; i < 1024; i += 256)
        reinterpret_cast<float4*>(sW2)[i] = reinterpret_cast<const float4*>(W2)[i];

    {
        int r  = tid & 63;
        int kc = tid >> 6;
        const float4* cin4 = reinterpret_cast<const float4*>(cin + (size_t)(rowbase + r) * CO);
        #pragma unroll
        for (int m = 0; m < 4; m++) {
            float4 v = cin4[kc * 4 + m];
            int k0 = kc * 16 + m * 4;
            sX[(k0 + 0) * 64 + r] = silu_f(v.x);
            sX[(k0 + 1) * 64 + r] = silu_f(v.y);
            sX[(k0 + 2) * 64 + r] = silu_f(v.z);
            sX[(k0 + 3) * 64 + r] = silu_f(v.w);
        }
    }
    __syncthreads();

    int tr = tid & 15;
    int tc = tid >> 4;

    float acc[4][8];
    #pragma unroll
    for (int i = 0; i < 4; i++)
        #pragma unroll
        for (int j = 0; j < 8; j++) acc[i][j] = 0.f;

    const float4* sX4  = reinterpret_cast<const float4*>(sX);
    const float4* sW14 = reinterpret_cast<const float4*>(sW1);
    #pragma unroll 4
    for (int k = 0; k < 64; k++) {
        float4 a  = sX4[k * 16 + tr];
        float4 b0 = sW14[k * 32 + tc * 2];
        float4 b1 = sW14[k * 32 + tc * 2 + 1];
        float av[4] = {a.x, a.y, a.z, a.w};
        float bv[8] = {b0.x, b0.y, b0.z, b0.w, b1.x, b1.y, b1.z, b1.w};
        #pragma unroll
        for (int i = 0; i < 4; i++)
            #pragma unroll
            for (int j = 0; j < 8; j++)
                acc[i][j] = fmaf(av[i], bv[j], acc[i][j]);
    }

    float4* sH4 = reinterpret_cast<float4*>(sH);
    #pragma unroll
    for (int j = 0; j < 8; j++) {
        int col = tc * 8 + j;
        float4 v = make_float4(silu_f(acc[0][j]), silu_f(acc[1][j]),
                               silu_f(acc[2][j]), silu_f(acc[3][j]));
        sH4[col * 17 + tr] = v;
    }
    __syncthreads();

    float a20 = 0.f, a21 = 0.f, a22 = 0.f, a23 = 0.f;
    float a30 = 0.f, a31 = 0.f, a32 = 0.f, a33 = 0.f;
    const float2* sW22 = reinterpret_cast<const float2*>(sW2);
    #pragma unroll 8
    for (int k = 0; k < 128; k++) {
        float4 a = sH4[k * 17 + tr];
        float2 b = sW22[k * 16 + tc];
        a20 = fmaf(a.x, b.x, a20);
        a21 = fmaf(a.y, b.x, a21);
        a22 = fmaf(a.z, b.x, a22);
        a23 = fmaf(a.w, b.x, a23);
        a30 = fmaf(a.x, b.y, a30);
        a31 = fmaf(a.y, b.y, a31);
        a32 = fmaf(a.z, b.y, a32);
        a33 = fmaf(a.w, b.y, a33);
    }

    float* sOut = sX;
    int r0 = tr * 4;
    int c0 = tc * 2;
    sOut[(r0 + 0) * 32 + c0]     = a20;
    sOut[(r0 + 1) * 32 + c0]     = a21;
    sOut[(r0 + 2) * 32 + c0]     = a22;
    sOut[(r0 + 3) * 32 + c0]     = a23;
    sOut[(r0 + 0) * 32 + c0 + 1] = a30;
    sOut[(r0 + 1) * 32 + c0 + 1] = a31;
    sOut[(r0 + 2) * 32 + c0 + 1] = a32;
    sOut[(r0 + 3) * 32 + c0 + 1] = a33;
    __syncthreads();

    const float4* sOut4 = reinterpret_cast<const float4*>(sOut);
    float4* out4 = reinterpret_cast<float4*>(g_c);
    int nodebase = blockIdx.x * 4;
    #pragma unroll
    for (int mm = 0; mm < 2; mm++) {
        int m  = tid + mm * 256;
        int q  = m >> 7;
        int w  = m & 127;
        int i  = w >> 5;
        int l  = w & 31;
        int rr = l >> 1;
        int hf = l & 1;
        float4 vv = sOut4[(q * 16 + rr) * 8 + hf * 4 + i];
        out4[(size_t)(nodebase + q) * 128 + w] = vv;
    }
}

// ---------------- K3: fused triplet + edge + aggregation ------------------
// warp per edge; lane pair (2r, 2r+1) owns DR row r (16 h-values each).
__global__ __launch_bounds__(256) void fused_edge_kernel(
    const float* __restrict__ robs,
    const float* __restrict__ shbs,
    const int* __restrict__ idx_j,
    const int* __restrict__ idx_k,
    const int* __restrict__ e_kj,
    const int* __restrict__ edge_index) {
    int e    = (blockIdx.x * blockDim.x + threadIdx.x) >> 5;
    int lane = threadIdx.x & 31;
    if (e >= N_EDGES) return;

    const float4* c4 = reinterpret_cast<const float4*>(g_c);
    int hr = lane >> 1;

    // independent scalars up front (overlap with everything)
    int n   = g_cnt[e];
    int src = edge_index[e];
    int dst = edge_index[N_EDGES + e];
    float wr = robs[e * DR + hr];
    const int* sl = g_slot + e * SLOT_CAP;

    float tw[16];
    #pragma unroll
    for (int i = 0; i < 16; i++) tw[i] = 0.f;

    // -------- accumulate tw over this edge's triplets (no pointer chase) ----
    #pragma unroll 2
    for (int ii = 0; ii < n; ii++) {
        int t  = sl[ii];
        int j  = idx_j[t];
        int k  = idx_k[t];
        int kj = e_kj[t];
        float w = shbs[t * DR + hr] * robs[kj * DR + hr];

        float v[16];
        #pragma unroll
        for (int i = 0; i < 4; i++) {
            float4 a = c4[(size_t)k * 128 + i * 32 + lane];
            float4 b = c4[(size_t)j * 128 + i * 32 + lane];
            v[i*4+0] = fmaf(a.x, b.x, a.x);
            v[i*4+1] = fmaf(a.y, b.y, a.y);
            v[i*4+2] = fmaf(a.z, b.z, a.z);
            v[i*4+3] = fmaf(a.w, b.w, a.w);
        }
        float p0 = 0.f, p1 = 0.f, p2 = 0.f, p3 = 0.f;
        #pragma unroll
        for (int i = 0; i < 4; i++) {
            p0 = fmaf(v[i*4+0], v[i*4+0], p0);
            p1 = fmaf(v[i*4+1], v[i*4+1], p1);
            p2 = fmaf(v[i*4+2], v[i*4+2], p2);
            p3 = fmaf(v[i*4+3], v[i*4+3], p3);
        }
        float ss = (p0 + p1) + (p2 + p3);
        ss += __shfl_xor_sync(0xffffffffu, ss, 1);
        float scale = w / fmaxf(sqrtf(ss), 1e-12f);
        #pragma unroll
        for (int i = 0; i < 16; i++) tw[i] = fmaf(scale, v[i], tw[i]);
    }

    // -------- edge interaction --------
    float val[16];
    #pragma unroll
    for (int i = 0; i < 4; i++) {
        float4 a = c4[(size_t)dst * 128 + i * 32 + lane];
        float4 b = c4[(size_t)src * 128 + i * 32 + lane];
        val[i*4+0] = fmaf(a.x, b.x, a.x) * tw[i*4+0];
        val[i*4+1] = fmaf(a.y, b.y, a.y) * tw[i*4+1];
        val[i*4+2] = fmaf(a.z, b.z, a.z) * tw[i*4+2];
        val[i*4+3] = fmaf(a.w, b.w, a.w) * tw[i*4+3];
    }
    float p0 = 0.f, p1 = 0.f, p2 = 0.f, p3 = 0.f;
    #pragma unroll
    for (int i = 0; i < 4; i++) {
        p0 = fmaf(val[i*4+0], val[i*4+0], p0);
        p1 = fmaf(val[i*4+1], val[i*4+1], p1);
        p2 = fmaf(val[i*4+2], val[i*4+2], p2);
        p3 = fmaf(val[i*4+3], val[i*4+3], p3);
    }
    float ss = (p0 + p1) + (p2 + p3);
    ss += __shfl_xor_sync(0xffffffffu, ss, 1);
    float factor = wr / fmaxf(sqrtf(ss), 1e-12f);
    #pragma unroll
    for (int i = 0; i < 16; i++) val[i] *= factor;

    // -------- fold: sum over the 16 rows --------
    #pragma unroll
    for (int st = 0; st < 4; st++) {
        const int s  = 2 << st;
        const int n2 = 8 >> st;
        bool up = (lane & s) != 0;
        #pragma unroll
        for (int m = 0; m < n2; m++) {
            float send = up ? val[m] : val[m + n2];
            float recv = __shfl_xor_sync(0xffffffffu, send, s);
            val[m] = (up ? val[m + n2] : val[m]) + recv;
        }
    }
    float acc = val[0];
    int idx = ((lane >> 1) & 1) * 8 + ((lane >> 2) & 1) * 4 +
              ((lane >> 3) & 1) * 2 + ((lane >> 4) & 1);
    int h = (lane & 1) * 16 + idx;

    float sq = acc * acc;
    #pragma unroll
    for (int m = 1; m < 32; m <<= 1) sq += __shfl_xor_sync(0xffffffffu, sq, m);
    float rd = acc / fmaxf(sqrtf(sq), 1e-12f);

    atomicAdd(&g_agg[src * DOWN + h], g_xd[dst * DOWN + h] * rd);
}

// ---------------- K5: up-projection ---------------------------------------
__global__ void up_kernel(const float* __restrict__ Wup,
                          float* __restrict__ out) {
    __shared__ float sW[DOWN * HID];
    __shared__ float sA[16 * DOWN];
    int t = threadIdx.x;
    for (int i = t; i < DOWN * HID; i += 128) sW[i] = Wup[i];
    int base = blockIdx.x * 16;
    for (int i = t; i < 512; i += 128) sA[i] = g_agg[base * DOWN + i];
    __syncthreads();

    for (int n = 0; n < 16; n++) {
        float acc = 0.f;
        #pragma unroll 8
        for (int d = 0; d < DOWN; d++)
            acc = fmaf(sA[n * DOWN + d], sW[d * HID + t], acc);
        out[(base + n) * HID + t] = acc;
    }
}

// ---------------- launch ---------------------------------------------------
extern "C" void kernel_launch(void* const* d_in, const int* in_sizes, int n_in,
                              void* d_out, int out_size) {
    const float* x      = (const float*)d_in[0];
    const float* robs   = (const float*)d_in[1];
    const float* shbs   = (const float*)d_in[2];
    const float* coeffs = (const float*)d_in[3];
    const int*   eidx   = (const int*)d_in[4];
    const int*   idx_j  = (const int*)d_in[5];
    const int*   idx_k  = (const int*)d_in[6];
    const int*   e_kj   = (const int*)d_in[7];
    const int*   e_ji   = (const int*)d_in[8];
    const float* Wn1    = (const float*)d_in[9];
    const float* bn1    = (const float*)d_in[10];
    const float* Wn2    = (const float*)d_in[11];
    const float* bn2    = (const float*)d_in[12];
    const float* Wc1    = (const float*)d_in[13];
    const float* Wc2    = (const float*)d_in[14];
    const float* Wup    = (const float*)d_in[15];
    float* out = (float*)d_out;

    cudaFuncSetAttribute(node_mlp_kernel, cudaFuncAttributeMaxDynamicSharedMemorySize, 21664 * 4);
    cudaFuncSetAttribute(co_mlp_kernel,   cudaFuncAttributeMaxDynamicSharedMemorySize, CO_SMEM * 4);

    init_kernel<<<(840000 + 255) / 256, 256>>>();
    fill_kernel<<<(N_TRIP + 255) / 256, 256>>>(e_ji);

    node_mlp_kernel<<<1250, 128, 21664 * 4>>>(x, Wn1, bn1, Wn2, bn2);

    co_mlp_kernel<<<5000, 256, CO_SMEM * 4>>>(coeffs, Wc1, Wc2);

    fused_edge_kernel<<<N_EDGES / 8, 256>>>(robs, shbs, idx_j, idx_k, e_kj, eidx);

    up_kernel<<<1250, 128>>>(Wup, out);
}